// round 1
// baseline (speedup 1.0000x reference)
#include <cuda_runtime.h>
#include <cuda_bf16.h>
#include <math.h>

// Problem constants (fixed shapes)
#define BB 8
#define NN 1024
#define DD 768
#define HH 4
#define MM (BB * NN)          // 8192 rows total
#define ALPHA_LRELU 0.2f

// ----------------------------------------------------------------------------
// Scratch (device globals; no allocations allowed)
// ----------------------------------------------------------------------------
__device__ float g_Wh[(long)HH * MM * DD];       // per-head Wh  [h][r][d]
__device__ float g_xx[(long)MM * (HH * DD)];     // concat heads [r][h*D+d]
__device__ float g_Who[(long)MM * DD];           // out-layer Wh
__device__ float g_P[(long)HH * BB * NN * NN];   // attention weights (reused for out layer)
__device__ float g_f1[HH * MM];
__device__ float g_f2[HH * MM];
__device__ float g_f1o[MM];
__device__ float g_f2o[MM];

// ----------------------------------------------------------------------------
// Fast FMA-only expf (avoids MUFU bottleneck). Valid for x <= 0-ish range,
// accuracy ~1e-7 relative.
// ----------------------------------------------------------------------------
__device__ __forceinline__ float fexp(float x) {
    float y = x * 1.4426950408889634f;       // log2(e)
    y = fmaxf(y, -126.0f);
    float r = y + 12582912.0f;               // 1.5 * 2^23 round trick
    float fn = r - 12582912.0f;              // round(y)
    int   n  = (int)fn;
    float f  = y - fn;                       // in [-0.5, 0.5]
    float p = 1.3400e-3f;
    p = fmaf(p, f, 9.6784351e-3f);
    p = fmaf(p, f, 5.5503426e-2f);
    p = fmaf(p, f, 2.4022652e-1f);
    p = fmaf(p, f, 6.9314718e-1f);
    p = fmaf(p, f, 1.0f);
    return __int_as_float(__float_as_int(p) + (n << 23));
}

// ----------------------------------------------------------------------------
// Tiled SGEMM: C[M,Nc] = A[M,K] @ B[K,Nc], row-major, all dims tile-exact.
// BM=BN=128, BK=8, 256 threads, 8x8 microtile.
// EPI: 0=store, 1=elu, 2=elu + residual R
// Batch offsets: A += z*sA; B += z*sB; C += (z%zmod)*sC + (z/zmod)*sC2; R += z*sR
// ----------------------------------------------------------------------------
template <int EPI>
__global__ void __launch_bounds__(256)
sgemm_kernel(const float* __restrict__ A, const float* __restrict__ B,
             float* __restrict__ C, const float* __restrict__ R,
             int M, int Nc, int K, int ldc,
             long sA, long sB, long sC, long sC2, int zmod, long sR)
{
    int z = blockIdx.z;
    const float* Ab = A + (long)z * sA;
    const float* Bb = B + (long)z * sB;
    float* Cb = C + (long)(z % zmod) * sC + (long)(z / zmod) * sC2;
    const float* Rb = (EPI == 2) ? (R + (long)z * sR) : nullptr;

    __shared__ __align__(16) float As[8][128];
    __shared__ __align__(16) float Bs[8][128];

    int tid  = threadIdx.x;
    int brow = blockIdx.y * 128;
    int bcol = blockIdx.x * 128;

    int aRow = tid >> 1;            // 0..127
    int aCol = (tid & 1) * 4;       // 0 or 4
    int bRow = tid >> 5;            // 0..7
    int bCol = (tid & 31) * 4;      // 0..124

    int tx = (tid & 15) * 8;
    int ty = (tid >> 4) * 8;

    float acc[8][8];
    #pragma unroll
    for (int i = 0; i < 8; i++)
        #pragma unroll
        for (int j = 0; j < 8; j++) acc[i][j] = 0.0f;

    for (int k0 = 0; k0 < K; k0 += 8) {
        float4 av = *(const float4*)(Ab + (long)(brow + aRow) * K + k0 + aCol);
        float4 bv = *(const float4*)(Bb + (long)(k0 + bRow) * Nc + bcol + bCol);
        As[aCol + 0][aRow] = av.x;
        As[aCol + 1][aRow] = av.y;
        As[aCol + 2][aRow] = av.z;
        As[aCol + 3][aRow] = av.w;
        *(float4*)&Bs[bRow][bCol] = bv;
        __syncthreads();

        #pragma unroll
        for (int kk = 0; kk < 8; kk++) {
            float4 a0 = *(const float4*)&As[kk][ty];
            float4 a1 = *(const float4*)&As[kk][ty + 4];
            float4 b0 = *(const float4*)&Bs[kk][tx];
            float4 b1 = *(const float4*)&Bs[kk][tx + 4];
            float ar[8] = {a0.x, a0.y, a0.z, a0.w, a1.x, a1.y, a1.z, a1.w};
            float br[8] = {b0.x, b0.y, b0.z, b0.w, b1.x, b1.y, b1.z, b1.w};
            #pragma unroll
            for (int i = 0; i < 8; i++)
                #pragma unroll
                for (int j = 0; j < 8; j++)
                    acc[i][j] = fmaf(ar[i], br[j], acc[i][j]);
        }
        __syncthreads();
    }

    #pragma unroll
    for (int i = 0; i < 8; i++) {
        long row = brow + ty + i;
        #pragma unroll
        for (int j = 0; j < 8; j += 4) {
            float v[4];
            #pragma unroll
            for (int q = 0; q < 4; q++) {
                float x = acc[i][j + q];
                if (EPI >= 1) x = (x > 0.0f) ? x : expm1f(x);
                v[q] = x;
            }
            long cidx = row * ldc + bcol + tx + j;
            if (EPI == 2) {
                float4 rv = *(const float4*)&Rb[cidx];
                v[0] += rv.x; v[1] += rv.y; v[2] += rv.z; v[3] += rv.w;
            }
            float4 o = make_float4(v[0], v[1], v[2], v[3]);
            *(float4*)&Cb[cidx] = o;
        }
    }
}

// ----------------------------------------------------------------------------
// f1/f2: per-row dot products with attention vector a (a: [nh][2D])
// grid (M, nh), 256 threads
// ----------------------------------------------------------------------------
__global__ void __launch_bounds__(256)
fvec_kernel(const float* __restrict__ Wh, const float* __restrict__ a,
            float* __restrict__ f1, float* __restrict__ f2)
{
    int r = blockIdx.x;
    int h = blockIdx.y;
    int t = threadIdx.x;
    const float* w  = Wh + ((long)h * MM + r) * DD;
    const float* ah = a + (long)h * 2 * DD;

    float s1 = 0.0f, s2 = 0.0f;
    for (int d = t; d < DD; d += 256) {
        float v = w[d];
        s1 += v * ah[d];
        s2 += v * ah[DD + d];
    }
    __shared__ float r1[256], r2[256];
    r1[t] = s1; r2[t] = s2;
    __syncthreads();
    for (int s = 128; s > 0; s >>= 1) {
        if (t < s) { r1[t] += r1[t + s]; r2[t] += r2[t + s]; }
        __syncthreads();
    }
    if (t == 0) {
        f1[(long)h * MM + r] = r1[0];
        f2[(long)h * MM + r] = r2[0];
    }
}

// ----------------------------------------------------------------------------
// Masked-softmax rows: for each (b,i), all heads: P[h,b,i,j] = softmax over j
// of lrelu(f1[i]+f2[j]) masked by adj. Adjacency row cached in smem.
// ----------------------------------------------------------------------------
__global__ void __launch_bounds__(256)
attn_rows_kernel(const int* __restrict__ adj,
                 const float* __restrict__ f1, const float* __restrict__ f2,
                 float* __restrict__ P, int nheads)
{
    int r = blockIdx.x;          // 0..8191
    int b = r >> 10;
    int i = r & 1023;
    int t = threadIdx.x;

    __shared__ int   adjrow[NN];
    __shared__ float srow[NN];
    __shared__ float red[256];

    const int* arow = adj + ((long)b * NN + i) * NN;
    for (int j = t; j < NN; j += 256) adjrow[j] = arow[j];
    __syncthreads();

    for (int h = 0; h < nheads; h++) {
        float f1v = f1[(long)h * MM + r];
        const float* f2h = f2 + (long)h * MM + (long)b * NN;

        // pass 1: scores + masked max
        float lmax = -INFINITY;
        #pragma unroll
        for (int j = t; j < NN; j += 256) {
            float s = f1v + f2h[j];
            s = (s > 0.0f) ? s : ALPHA_LRELU * s;
            srow[j] = s;
            if (adjrow[j]) lmax = fmaxf(lmax, s);
        }
        red[t] = lmax;
        __syncthreads();
        for (int s = 128; s > 0; s >>= 1) {
            if (t < s) red[t] = fmaxf(red[t], red[t + s]);
            __syncthreads();
        }
        float m = red[0];
        __syncthreads();

        // pass 2: exp + denom
        float lsum = 0.0f;
        #pragma unroll
        for (int j = t; j < NN; j += 256) {
            float w = adjrow[j] ? fexp(srow[j] - m) : 0.0f;
            srow[j] = w;
            lsum += w;
        }
        red[t] = lsum;
        __syncthreads();
        for (int s = 128; s > 0; s >>= 1) {
            if (t < s) red[t] += red[t + s];
            __syncthreads();
        }
        float rd = 1.0f / red[0];
        __syncthreads();

        // pass 3: normalized write
        float* Prow = P + ((((long)h * BB + b) * NN) + i) * NN;
        #pragma unroll
        for (int j = t; j < NN; j += 256) Prow[j] = srow[j] * rd;
        __syncthreads();
    }
}

// ----------------------------------------------------------------------------
// Classifier: scores[r] = sigmoid(yy[r,:]@w + b) * mask[r]
// ----------------------------------------------------------------------------
__global__ void __launch_bounds__(256)
classifier_kernel(const float* __restrict__ yy, const float* __restrict__ wc,
                  const float* __restrict__ bc, const float* __restrict__ mask,
                  float* __restrict__ scores)
{
    int r = blockIdx.x;
    int t = threadIdx.x;
    const float* y = yy + (long)r * DD;
    float s = 0.0f;
    for (int d = t; d < DD; d += 256) s += y[d] * wc[d];
    __shared__ float red[256];
    red[t] = s;
    __syncthreads();
    for (int k = 128; k > 0; k >>= 1) {
        if (t < k) red[t] += red[t + k];
        __syncthreads();
    }
    if (t == 0) {
        float v = red[0] + bc[0];
        scores[r] = (1.0f / (1.0f + expf(-v))) * mask[r];
    }
}

// ----------------------------------------------------------------------------
// Launch
// ----------------------------------------------------------------------------
extern "C" void kernel_launch(void* const* d_in, const int* in_sizes, int n_in,
                              void* d_out, int out_size)
{
    const float* input_emb = (const float*)d_in[0];   // [B,N,D]
    const int*   adj       = (const int*)d_in[1];     // [B,N,N]
    const float* mask_node = (const float*)d_in[2];   // [B,N]
    const float* W_heads   = (const float*)d_in[3];   // [H,D,D]
    const float* a_heads   = (const float*)d_in[4];   // [H,2D,1]
    const float* W_out     = (const float*)d_in[5];   // [H*D,D]
    const float* a_out     = (const float*)d_in[6];   // [2D,1]
    const float* w_cls     = (const float*)d_in[7];   // [D,1]
    const float* b_cls     = (const float*)d_in[8];   // [1]

    float* yy     = (float*)d_out;                    // [B,N,D]
    float* scores = (float*)d_out + (long)MM * DD;    // [B,N]

    float *p_Wh, *p_xx, *p_Who, *p_P, *p_f1, *p_f2, *p_f1o, *p_f2o;
    cudaGetSymbolAddress((void**)&p_Wh,  g_Wh);
    cudaGetSymbolAddress((void**)&p_xx,  g_xx);
    cudaGetSymbolAddress((void**)&p_Who, g_Who);
    cudaGetSymbolAddress((void**)&p_P,   g_P);
    cudaGetSymbolAddress((void**)&p_f1,  g_f1);
    cudaGetSymbolAddress((void**)&p_f2,  g_f2);
    cudaGetSymbolAddress((void**)&p_f1o, g_f1o);
    cudaGetSymbolAddress((void**)&p_f2o, g_f2o);

    const int ZBIG = 1 << 30;

    // 1) Wh[h] = X @ W_heads[h]   (M=8192, Nc=768, K=768, 4 heads)
    {
        dim3 grid(DD / 128, MM / 128, HH);
        sgemm_kernel<0><<<grid, 256>>>(input_emb, W_heads, p_Wh, nullptr,
                                       MM, DD, DD, DD,
                                       0L, (long)DD * DD, (long)MM * DD, 0L, ZBIG, 0L);
    }

    // 2) f1/f2 per head
    fvec_kernel<<<dim3(MM, HH), 256>>>(p_Wh, a_heads, p_f1, p_f2);

    // 3) attention weights per head -> P
    attn_rows_kernel<<<MM, 256>>>(adj, p_f1, p_f2, p_P, HH);

    // 4) xx[.., h*D:+D] = elu(P[h,b] @ Wh[h,b])   (32 batches, M=1024, K=1024)
    {
        dim3 grid(DD / 128, NN / 128, HH * BB);
        sgemm_kernel<1><<<grid, 256>>>(p_P, p_Wh, p_xx, nullptr,
                                       NN, DD, NN, HH * DD,
                                       (long)NN * NN, (long)NN * DD,
                                       (long)NN * HH * DD, (long)DD, BB, 0L);
    }

    // 5) Who = xx @ W_out   (M=8192, Nc=768, K=3072)
    {
        dim3 grid(DD / 128, MM / 128, 1);
        sgemm_kernel<0><<<grid, 256>>>(p_xx, W_out, p_Who, nullptr,
                                       MM, DD, HH * DD, DD,
                                       0L, 0L, 0L, 0L, ZBIG, 0L);
    }

    // 6) f1o/f2o
    fvec_kernel<<<dim3(MM, 1), 256>>>(p_Who, a_out, p_f1o, p_f2o);

    // 7) out-layer attention weights -> P (reuse, nheads=1)
    attn_rows_kernel<<<MM, 256>>>(adj, p_f1o, p_f2o, p_P, 1);

    // 8) yy = elu(P[b] @ Who[b]) + input_emb   (8 batches)
    {
        dim3 grid(DD / 128, NN / 128, BB);
        sgemm_kernel<2><<<grid, 256>>>(p_P, p_Who, yy, input_emb,
                                       NN, DD, NN, DD,
                                       (long)NN * NN, (long)NN * DD,
                                       (long)NN * DD, 0L, ZBIG, (long)NN * DD);
    }

    // 9) classifier
    classifier_kernel<<<MM, 256>>>(yy, w_cls, b_cls, mask_node, scores);

    (void)in_sizes; (void)n_in; (void)out_size;
}

// round 3
// speedup vs baseline: 2.3064x; 2.3064x over previous
#include <cuda_runtime.h>
#include <cuda_bf16.h>
#include <math.h>
#include <stdint.h>

// Problem constants
#define BB 8
#define NN 1024
#define DD 768
#define HH 4
#define MM (BB * NN)
#define ALPHA_LRELU 0.2f

// ----------------------------------------------------------------------------
// Scratch (device globals)
// ----------------------------------------------------------------------------
__device__ float g_Xr[(long)MM * DD];                 // tf32-rounded input
__device__ float g_Wh[(long)HH * MM * DD];            // per-head Wh (rounded)
__device__ float g_WhT[(long)HH * BB * DD * NN];      // Wh^T per (h,b)
__device__ float g_xx[(long)MM * (HH * DD)];          // concat heads (rounded)
__device__ float g_Who[(long)MM * DD];                // out-layer Wh (rounded)
__device__ float g_WhoT[(long)BB * DD * NN];
__device__ float g_WtH[(long)HH * DD * DD];           // W_heads^T (rounded)
__device__ float g_WoT[(long)DD * HH * DD];           // W_out^T (rounded)
__device__ float g_P[(long)HH * BB * NN * NN];        // attention probs (rounded)
__device__ float g_f1[HH * MM];
__device__ float g_f2[HH * MM];
__device__ float g_f1o[MM];
__device__ float g_f2o[MM];

// ----------------------------------------------------------------------------
// helpers
// ----------------------------------------------------------------------------
__device__ __forceinline__ uint32_t smem_u32(const void* p) {
    uint32_t a;
    asm("{ .reg .u64 t; cvta.to.shared.u64 t, %1; cvt.u32.u64 %0, t; }" : "=r"(a) : "l"(p));
    return a;
}
__device__ __forceinline__ float totf32(float x) {
    uint32_t u;
    asm("cvt.rna.tf32.f32 %0, %1;" : "=r"(u) : "f"(x));
    return __uint_as_float(u);
}

#define CP16(dst, src) asm volatile("cp.async.cg.shared.global [%0], [%1], 16;" :: "r"(dst), "l"(src))
#define CP_COMMIT()    asm volatile("cp.async.commit_group;" ::: "memory")
#define CP_WAIT1()     asm volatile("cp.async.wait_group 1;" ::: "memory")
#define CP_WAIT0()     asm volatile("cp.async.wait_group 0;" ::: "memory")

// ----------------------------------------------------------------------------
// tf32 mma.sync GEMM: C[M,Nc] = A[M,K] @ Bt[Nc,K]^T (both K-major)
// 128x128 CTA tile, 8 warps (64x32 each), KT=32, 3-stage cp.async pipeline.
// Smem rows padded to 40 floats -> conflict-free fragment gathers.
// EPI: 0 = store rounded, 1 = elu + round, 2 = elu + residual (fp32)
// ----------------------------------------------------------------------------
#define KT 32
#define STAGES 3
#define APAD 40
#define TILE_F (128 * APAD)
#define STAGE_F (2 * TILE_F)
#define GEMM_SMEM (STAGES * STAGE_F * 4)

template <int EPI>
__global__ void __launch_bounds__(256, 1)
mma_gemm(const float* __restrict__ A, const float* __restrict__ B,
         float* __restrict__ C, const float* __restrict__ R,
         int K, int ldc, long sA, long sB, long sC, long sC2, int zmod, long sR)
{
    extern __shared__ float sm[];
    uint32_t sb = smem_u32(sm);
    int tid = threadIdx.x;
    int l = tid & 31;
    int w = tid >> 5;

    int z = blockIdx.z;
    const float* Ab = A + (long)z * sA;
    const float* Bb = B + (long)z * sB;
    float* Cb = C + (long)(z % zmod) * sC + (long)(z / zmod) * sC2;
    const float* Rb = (EPI == 2) ? (R + (long)z * sR) : nullptr;

    int brow = blockIdx.y * 128;
    int bcol = blockIdx.x * 128;
    int m0 = (w & 1) * 64;       // warp m-offset in tile
    int n0 = (w >> 1) * 32;      // warp n-offset in tile

    float c[4][4][4];
    #pragma unroll
    for (int i = 0; i < 4; i++)
        #pragma unroll
        for (int j = 0; j < 4; j++)
            #pragma unroll
            for (int q = 0; q < 4; q++) c[i][j][q] = 0.0f;

    int nk = K / KT;
    int qrow = tid >> 3;                 // base row (thread loads rows qrow + 32*i)
    int qcol = (tid & 7) * 4;            // float offset within 32-float row

    // ---- stage loader ----
    auto load_stage = [&](int pf) {
        int buf = pf % STAGES;
        uint32_t dA = sb + (buf * STAGE_F) * 4;
        uint32_t dB = dA + TILE_F * 4;
        long kof = (long)pf * KT + qcol;
        #pragma unroll
        for (int i = 0; i < 4; i++) {
            int row = qrow + i * 32;
            CP16(dA + (row * APAD + qcol) * 4, Ab + (long)(brow + row) * K + kof);
            CP16(dB + (row * APAD + qcol) * 4, Bb + (long)(bcol + row) * K + kof);
        }
        CP_COMMIT();
    };

    // prologue: 2 stages in flight
    load_stage(0);
    if (nk > 1) load_stage(1);

    for (int s = 0; s < nk; s++) {
        if (s + 1 < nk) { CP_WAIT1(); } else { CP_WAIT0(); }
        __syncthreads();
        if (s + 2 < nk) load_stage(s + 2);

        const float* As = sm + (s % STAGES) * STAGE_F;
        const float* Bs = As + TILE_F;

        #pragma unroll
        for (int kk = 0; kk < 4; kk++) {
            int k0 = kk * 8 + (l & 3);
            float af[4][4], bf[4][2];
            #pragma unroll
            for (int mi = 0; mi < 4; mi++) {
                int r = m0 + mi * 16 + (l >> 2);
                af[mi][0] = As[r * APAD + k0];
                af[mi][1] = As[(r + 8) * APAD + k0];
                af[mi][2] = As[r * APAD + k0 + 4];
                af[mi][3] = As[(r + 8) * APAD + k0 + 4];
            }
            #pragma unroll
            for (int ni = 0; ni < 4; ni++) {
                int cn = n0 + ni * 8 + (l >> 2);
                bf[ni][0] = Bs[cn * APAD + k0];
                bf[ni][1] = Bs[cn * APAD + k0 + 4];
            }
            #pragma unroll
            for (int mi = 0; mi < 4; mi++)
                #pragma unroll
                for (int ni = 0; ni < 4; ni++)
                    asm volatile(
                        "mma.sync.aligned.m16n8k8.row.col.f32.tf32.tf32.f32 "
                        "{%0,%1,%2,%3}, {%4,%5,%6,%7}, {%8,%9}, {%0,%1,%2,%3};"
                        : "+f"(c[mi][ni][0]), "+f"(c[mi][ni][1]),
                          "+f"(c[mi][ni][2]), "+f"(c[mi][ni][3])
                        : "r"(__float_as_uint(af[mi][0])), "r"(__float_as_uint(af[mi][1])),
                          "r"(__float_as_uint(af[mi][2])), "r"(__float_as_uint(af[mi][3])),
                          "r"(__float_as_uint(bf[ni][0])), "r"(__float_as_uint(bf[ni][1])));
        }
    }

    // ---- epilogue ----
    #pragma unroll
    for (int mi = 0; mi < 4; mi++) {
        #pragma unroll
        for (int hh = 0; hh < 2; hh++) {
            long rg = brow + m0 + mi * 16 + (l >> 2) + hh * 8;
            #pragma unroll
            for (int ni = 0; ni < 4; ni++) {
                float v0 = c[mi][ni][hh * 2 + 0];
                float v1 = c[mi][ni][hh * 2 + 1];
                if (EPI >= 1) {
                    v0 = (v0 > 0.0f) ? v0 : expm1f(v0);
                    v1 = (v1 > 0.0f) ? v1 : expm1f(v1);
                }
                if (EPI <= 1) { v0 = totf32(v0); v1 = totf32(v1); }
                long ci = rg * ldc + bcol + n0 + ni * 8 + (l & 3) * 2;
                if (EPI == 2) {
                    float2 rv = *(const float2*)&Rb[ci];
                    v0 += rv.x; v1 += rv.y;
                }
                float2 o; o.x = v0; o.y = v1;
                *(float2*)&Cb[ci] = o;
            }
        }
    }
}

// ----------------------------------------------------------------------------
// elementwise tf32-round copy
// ----------------------------------------------------------------------------
__global__ void __launch_bounds__(256)
round_copy(const float4* __restrict__ in, float4* __restrict__ out, long n4)
{
    long i = (long)blockIdx.x * 256 + threadIdx.x;
    if (i < n4) {
        float4 v = in[i];
        v.x = totf32(v.x); v.y = totf32(v.y); v.z = totf32(v.z); v.w = totf32(v.w);
        out[i] = v;
    }
}

// ----------------------------------------------------------------------------
// batched tiled transpose: [z][R][C] -> [z][C][R], optional tf32 rounding
// ----------------------------------------------------------------------------
__global__ void __launch_bounds__(256)
transpose_kernel(const float* __restrict__ in, float* __restrict__ out,
                 int R, int C, int do_round)
{
    __shared__ float t[32][33];
    long z = blockIdx.z;
    in  += z * (long)R * C;
    out += z * (long)R * C;
    int x = blockIdx.x * 32;
    int y = blockIdx.y * 32;
    int tx = threadIdx.x & 31, ty = threadIdx.x >> 5;
    #pragma unroll
    for (int i = 0; i < 32; i += 8)
        t[ty + i][tx] = in[(long)(y + ty + i) * C + x + tx];
    __syncthreads();
    #pragma unroll
    for (int i = 0; i < 32; i += 8) {
        float v = t[tx][ty + i];
        if (do_round) v = totf32(v);
        out[(long)(x + ty + i) * R + y + tx] = v;
    }
}

// ----------------------------------------------------------------------------
// fast exp (FMA only)
// ----------------------------------------------------------------------------
__device__ __forceinline__ float fexp(float x) {
    float y = x * 1.4426950408889634f;
    y = fmaxf(y, -126.0f);
    float r = y + 12582912.0f;
    float fn = r - 12582912.0f;
    int   n  = (int)fn;
    float f  = y - fn;
    float p = 1.3400e-3f;
    p = fmaf(p, f, 9.6784351e-3f);
    p = fmaf(p, f, 5.5503426e-2f);
    p = fmaf(p, f, 2.4022652e-1f);
    p = fmaf(p, f, 6.9314718e-1f);
    p = fmaf(p, f, 1.0f);
    return __int_as_float(__float_as_int(p) + (n << 23));
}

// ----------------------------------------------------------------------------
// f1/f2 per-row dot products
// ----------------------------------------------------------------------------
__global__ void __launch_bounds__(256)
fvec_kernel(const float* __restrict__ Wh, const float* __restrict__ a,
            float* __restrict__ f1, float* __restrict__ f2)
{
    int r = blockIdx.x;
    int h = blockIdx.y;
    int t = threadIdx.x;
    const float* w  = Wh + ((long)h * MM + r) * DD;
    const float* ah = a + (long)h * 2 * DD;
    float s1 = 0.0f, s2 = 0.0f;
    for (int d = t; d < DD; d += 256) {
        float v = w[d];
        s1 += v * ah[d];
        s2 += v * ah[DD + d];
    }
    __shared__ float r1[256], r2[256];
    r1[t] = s1; r2[t] = s2;
    __syncthreads();
    for (int s = 128; s > 0; s >>= 1) {
        if (t < s) { r1[t] += r1[t + s]; r2[t] += r2[t + s]; }
        __syncthreads();
    }
    if (t == 0) {
        f1[(long)h * MM + r] = r1[0];
        f2[(long)h * MM + r] = r2[0];
    }
}

// ----------------------------------------------------------------------------
// masked softmax rows -> P (tf32-rounded)
// ----------------------------------------------------------------------------
__global__ void __launch_bounds__(256)
attn_rows_kernel(const int* __restrict__ adj,
                 const float* __restrict__ f1, const float* __restrict__ f2,
                 float* __restrict__ P, int nheads)
{
    int r = blockIdx.x;
    int b = r >> 10;
    int t = threadIdx.x;

    __shared__ int   adjrow[NN];
    __shared__ float srow[NN];
    __shared__ float red[256];

    const int* arow = adj + (long)r * NN;
    for (int j = t; j < NN; j += 256) adjrow[j] = arow[j];
    __syncthreads();

    for (int h = 0; h < nheads; h++) {
        float f1v = f1[(long)h * MM + r];
        const float* f2h = f2 + (long)h * MM + (long)b * NN;

        float lmax = -INFINITY;
        #pragma unroll
        for (int j = t; j < NN; j += 256) {
            float s = f1v + f2h[j];
            s = (s > 0.0f) ? s : ALPHA_LRELU * s;
            srow[j] = s;
            if (adjrow[j]) lmax = fmaxf(lmax, s);
        }
        red[t] = lmax;
        __syncthreads();
        for (int s = 128; s > 0; s >>= 1) {
            if (t < s) red[t] = fmaxf(red[t], red[t + s]);
            __syncthreads();
        }
        float m = red[0];
        __syncthreads();

        float lsum = 0.0f;
        #pragma unroll
        for (int j = t; j < NN; j += 256) {
            float wv = adjrow[j] ? fexp(srow[j] - m) : 0.0f;
            srow[j] = wv;
            lsum += wv;
        }
        red[t] = lsum;
        __syncthreads();
        for (int s = 128; s > 0; s >>= 1) {
            if (t < s) red[t] += red[t + s];
            __syncthreads();
        }
        float rd = 1.0f / red[0];
        __syncthreads();

        float* Prow = P + (((long)h * BB + b) * NN + (r & 1023)) * NN;
        #pragma unroll
        for (int j = t; j < NN; j += 256) Prow[j] = totf32(srow[j] * rd);
        __syncthreads();
    }
}

// ----------------------------------------------------------------------------
// classifier
// ----------------------------------------------------------------------------
__global__ void __launch_bounds__(256)
classifier_kernel(const float* __restrict__ yy, const float* __restrict__ wc,
                  const float* __restrict__ bc, const float* __restrict__ mask,
                  float* __restrict__ scores)
{
    int r = blockIdx.x;
    int t = threadIdx.x;
    const float* y = yy + (long)r * DD;
    float s = 0.0f;
    for (int d = t; d < DD; d += 256) s += y[d] * wc[d];
    __shared__ float red[256];
    red[t] = s;
    __syncthreads();
    for (int k = 128; k > 0; k >>= 1) {
        if (t < k) red[t] += red[t + k];
        __syncthreads();
    }
    if (t == 0) {
        float v = red[0] + bc[0];
        scores[r] = (1.0f / (1.0f + expf(-v))) * mask[r];
    }
}

// ----------------------------------------------------------------------------
// launch
// ----------------------------------------------------------------------------
extern "C" void kernel_launch(void* const* d_in, const int* in_sizes, int n_in,
                              void* d_out, int out_size)
{
    const float* input_emb = (const float*)d_in[0];
    const int*   adj       = (const int*)d_in[1];
    const float* mask_node = (const float*)d_in[2];
    const float* W_heads   = (const float*)d_in[3];
    const float* a_heads   = (const float*)d_in[4];
    const float* W_out     = (const float*)d_in[5];
    const float* a_out     = (const float*)d_in[6];
    const float* w_cls     = (const float*)d_in[7];
    const float* b_cls     = (const float*)d_in[8];

    float* yy     = (float*)d_out;
    float* scores = (float*)d_out + (long)MM * DD;

    float *p_Xr, *p_Wh, *p_WhT, *p_xx, *p_Who, *p_WhoT, *p_WtH, *p_WoT, *p_P;
    float *p_f1, *p_f2, *p_f1o, *p_f2o;
    cudaGetSymbolAddress((void**)&p_Xr,   g_Xr);
    cudaGetSymbolAddress((void**)&p_Wh,   g_Wh);
    cudaGetSymbolAddress((void**)&p_WhT,  g_WhT);
    cudaGetSymbolAddress((void**)&p_xx,   g_xx);
    cudaGetSymbolAddress((void**)&p_Who,  g_Who);
    cudaGetSymbolAddress((void**)&p_WhoT, g_WhoT);
    cudaGetSymbolAddress((void**)&p_WtH,  g_WtH);
    cudaGetSymbolAddress((void**)&p_WoT,  g_WoT);
    cudaGetSymbolAddress((void**)&p_P,    g_P);
    cudaGetSymbolAddress((void**)&p_f1,   g_f1);
    cudaGetSymbolAddress((void**)&p_f2,   g_f2);
    cudaGetSymbolAddress((void**)&p_f1o,  g_f1o);
    cudaGetSymbolAddress((void**)&p_f2o,  g_f2o);

    cudaFuncSetAttribute(mma_gemm<0>, cudaFuncAttributeMaxDynamicSharedMemorySize, GEMM_SMEM);
    cudaFuncSetAttribute(mma_gemm<1>, cudaFuncAttributeMaxDynamicSharedMemorySize, GEMM_SMEM);
    cudaFuncSetAttribute(mma_gemm<2>, cudaFuncAttributeMaxDynamicSharedMemorySize, GEMM_SMEM);

    const int ZBIG = 1 << 30;

    // 0) tf32-round input X
    {
        long n4 = (long)MM * DD / 4;
        round_copy<<<(unsigned)((n4 + 255) / 256), 256>>>((const float4*)input_emb, (float4*)p_Xr, n4);
    }
    // W_heads^T per head (rounded)
    transpose_kernel<<<dim3(DD / 32, DD / 32, HH), 256>>>(W_heads, p_WtH, DD, DD, 1);

    // 1) Wh[h] = Xr @ W_heads[h]  (rounded store)
    mma_gemm<0><<<dim3(DD / 128, MM / 128, HH), 256, GEMM_SMEM>>>(
        p_Xr, p_WtH, p_Wh, nullptr, DD, DD,
        0L, (long)DD * DD, (long)MM * DD, 0L, ZBIG, 0L);

    // 2) f1/f2
    fvec_kernel<<<dim3(MM, HH), 256>>>(p_Wh, a_heads, p_f1, p_f2);

    // 3) attention probs
    attn_rows_kernel<<<MM, 256>>>(adj, p_f1, p_f2, p_P, HH);

    // 3b) Wh^T per (h,b)
    transpose_kernel<<<dim3(DD / 32, NN / 32, HH * BB), 256>>>(p_Wh, p_WhT, NN, DD, 0);

    // 4) xx = elu(P @ Wh)  (rounded store)
    mma_gemm<1><<<dim3(DD / 128, NN / 128, HH * BB), 256, GEMM_SMEM>>>(
        p_P, p_WhT, p_xx, nullptr, NN, HH * DD,
        (long)NN * NN, (long)DD * NN,
        (long)NN * HH * DD, (long)DD, BB, 0L);

    // 4b) W_out^T (rounded)
    transpose_kernel<<<dim3(DD / 32, (HH * DD) / 32, 1), 256>>>(W_out, p_WoT, HH * DD, DD, 1);

    // 5) Who = xx @ W_out  (rounded store)
    mma_gemm<0><<<dim3(DD / 128, MM / 128, 1), 256, GEMM_SMEM>>>(
        p_xx, p_WoT, p_Who, nullptr, HH * DD, DD,
        0L, 0L, 0L, 0L, ZBIG, 0L);

    // 6) f1o/f2o
    fvec_kernel<<<dim3(MM, 1), 256>>>(p_Who, a_out, p_f1o, p_f2o);

    // 7) out-layer attention probs
    attn_rows_kernel<<<MM, 256>>>(adj, p_f1o, p_f2o, p_P, 1);

    // 7b) Who^T per b
    transpose_kernel<<<dim3(DD / 32, NN / 32, BB), 256>>>(p_Who, p_WhoT, NN, DD, 0);

    // 8) yy = elu(P @ Who) + input_emb  (fp32)
    mma_gemm<2><<<dim3(DD / 128, NN / 128, BB), 256, GEMM_SMEM>>>(
        p_P, p_WhoT, yy, input_emb, NN, DD,
        (long)NN * NN, (long)DD * NN,
        (long)NN * DD, 0L, ZBIG, (long)NN * DD);

    // 9) classifier
    classifier_kernel<<<MM, 256>>>(yy, w_cls, b_cls, mask_node, scores);

    (void)in_sizes; (void)n_in; (void)out_size;
}

// round 4
// speedup vs baseline: 3.6267x; 1.5724x over previous
#include <cuda_runtime.h>
#include <cuda_bf16.h>
#include <math.h>
#include <stdint.h>

// Problem constants
#define BB 8
#define NN 1024
#define DD 768
#define HH 4
#define MM (BB * NN)
#define ALPHA_LRELU 0.2f

// ----------------------------------------------------------------------------
// Scratch (device globals)
// ----------------------------------------------------------------------------
__device__ float g_Xr[(long)MM * DD];                 // tf32-rounded input
__device__ float g_Wr[(long)HH * DD * DD];            // rounded W_heads (row-major)
__device__ float g_WoR[(long)HH * DD * DD];           // rounded W_out (row-major)
__device__ float g_Wh[(long)HH * MM * DD];            // per-head Wh (rounded)
__device__ float g_xx[(long)MM * (HH * DD)];          // concat heads (rounded)
__device__ float g_Who[(long)MM * DD];                // out-layer Wh (rounded)
__device__ float g_P[(long)HH * BB * NN * NN];        // attention probs (rounded)
__device__ float g_f1[HH * MM];
__device__ float g_f2[HH * MM];
__device__ float g_f1o[MM];
__device__ float g_f2o[MM];

// ----------------------------------------------------------------------------
// helpers
// ----------------------------------------------------------------------------
__device__ __forceinline__ uint32_t smem_u32(const void* p) {
    uint32_t a;
    asm("{ .reg .u64 t; cvta.to.shared.u64 t, %1; cvt.u32.u64 %0, t; }" : "=r"(a) : "l"(p));
    return a;
}
__device__ __forceinline__ float totf32(float x) {
    uint32_t u;
    asm("cvt.rna.tf32.f32 %0, %1;" : "=r"(u) : "f"(x));
    return __uint_as_float(u);
}

#define CP16(dst, src) asm volatile("cp.async.cg.shared.global [%0], [%1], 16;" :: "r"(dst), "l"(src))
#define CP_COMMIT()    asm volatile("cp.async.commit_group;" ::: "memory")
#define CP_WAIT1()     asm volatile("cp.async.wait_group 1;" ::: "memory")
#define CP_WAIT0()     asm volatile("cp.async.wait_group 0;" ::: "memory")

// ----------------------------------------------------------------------------
// tf32 mma.sync GEMM: C[M,Nc] = A[M,K] @ B[K,Nc]   (A K-major, B row-major MN)
// 128x128 CTA tile, 8 warps (64x32), KT=32, 3-stage cp.async, 2 CTAs/SM.
// A smem [128][APAD=36], B smem [32][BPAD=136] -> conflict-free frag gathers.
// EPI: 0 = store rounded, 1 = elu + round, 2 = elu + residual (fp32)
// ----------------------------------------------------------------------------
#define KT 32
#define STAGES 3
#define APAD 36
#define BPAD 136
#define A_TILE_F (128 * APAD)          // 4608 floats
#define B_TILE_F (KT * BPAD)           // 4352 floats
#define STAGE_F (A_TILE_F + B_TILE_F)  // 8960 floats
#define GEMM_SMEM (STAGES * STAGE_F * 4)

template <int EPI>
__global__ void __launch_bounds__(256, 2)
mma_gemm(const float* __restrict__ A, const float* __restrict__ B,
         float* __restrict__ C, const float* __restrict__ R,
         int K, int ldb, int ldc,
         long sA, long sB, long sC, long sC2, int zmod, long sR)
{
    extern __shared__ float sm[];
    uint32_t sb = smem_u32(sm);
    int tid = threadIdx.x;
    int l = tid & 31;
    int w = tid >> 5;

    int z = blockIdx.z;
    const float* Ab = A + (long)z * sA;
    const float* Bb = B + (long)z * sB;
    float* Cb = C + (long)(z % zmod) * sC + (long)(z / zmod) * sC2;
    const float* Rb = (EPI == 2) ? (R + (long)z * sR) : nullptr;

    int brow = blockIdx.y * 128;
    int bcol = blockIdx.x * 128;
    int m0 = (w & 1) * 64;
    int n0 = (w >> 1) * 32;

    float c[4][4][4];
    #pragma unroll
    for (int i = 0; i < 4; i++)
        #pragma unroll
        for (int j = 0; j < 4; j++)
            #pragma unroll
            for (int q = 0; q < 4; q++) c[i][j][q] = 0.0f;

    int nk = K / KT;

    // A loader mapping: 128 rows x 8 chunks of 16B
    int aRow = tid >> 3;                 // 0..31 (+32*i)
    int aOff = (tid & 7) * 4;            // float offset in 32-float slab
    // B loader mapping: 32 rows x 32 chunks of 16B
    int bRow = tid >> 5;                 // 0..7 (+8*i)
    int bOff = (tid & 31) * 4;           // float offset in 128-float row

    auto load_stage = [&](int pf) {
        int buf = pf % STAGES;
        uint32_t dA = sb + (buf * STAGE_F) * 4;
        uint32_t dB = dA + A_TILE_F * 4;
        long kof = (long)pf * KT;
        #pragma unroll
        for (int i = 0; i < 4; i++) {
            int row = aRow + i * 32;
            CP16(dA + (row * APAD + aOff) * 4, Ab + (long)(brow + row) * K + kof + aOff);
        }
        #pragma unroll
        for (int i = 0; i < 4; i++) {
            int kr = bRow + i * 8;
            CP16(dB + (kr * BPAD + bOff) * 4, Bb + (kof + kr) * (long)ldb + bcol + bOff);
        }
        CP_COMMIT();
    };

    load_stage(0);
    load_stage(1);

    for (int s = 0; s < nk; s++) {
        if (s + 1 < nk) { CP_WAIT1(); } else { CP_WAIT0(); }
        __syncthreads();
        if (s + 2 < nk) load_stage(s + 2);

        const float* As = sm + (s % STAGES) * STAGE_F;
        const float* Bs = As + A_TILE_F;

        #pragma unroll
        for (int kk = 0; kk < 4; kk++) {
            int k0 = kk * 8 + (l & 3);
            float af[4][4], bf[4][2];
            #pragma unroll
            for (int mi = 0; mi < 4; mi++) {
                int r = m0 + mi * 16 + (l >> 2);
                af[mi][0] = As[r * APAD + k0];
                af[mi][1] = As[(r + 8) * APAD + k0];
                af[mi][2] = As[r * APAD + k0 + 4];
                af[mi][3] = As[(r + 8) * APAD + k0 + 4];
            }
            #pragma unroll
            for (int ni = 0; ni < 4; ni++) {
                int cn = n0 + ni * 8 + (l >> 2);
                bf[ni][0] = Bs[k0 * BPAD + cn];
                bf[ni][1] = Bs[(k0 + 4) * BPAD + cn];
            }
            #pragma unroll
            for (int mi = 0; mi < 4; mi++)
                #pragma unroll
                for (int ni = 0; ni < 4; ni++)
                    asm volatile(
                        "mma.sync.aligned.m16n8k8.row.col.f32.tf32.tf32.f32 "
                        "{%0,%1,%2,%3}, {%4,%5,%6,%7}, {%8,%9}, {%0,%1,%2,%3};"
                        : "+f"(c[mi][ni][0]), "+f"(c[mi][ni][1]),
                          "+f"(c[mi][ni][2]), "+f"(c[mi][ni][3])
                        : "r"(__float_as_uint(af[mi][0])), "r"(__float_as_uint(af[mi][1])),
                          "r"(__float_as_uint(af[mi][2])), "r"(__float_as_uint(af[mi][3])),
                          "r"(__float_as_uint(bf[ni][0])), "r"(__float_as_uint(bf[ni][1])));
        }
    }

    // epilogue (row-major C)
    #pragma unroll
    for (int mi = 0; mi < 4; mi++) {
        #pragma unroll
        for (int hh = 0; hh < 2; hh++) {
            long rg = brow + m0 + mi * 16 + (l >> 2) + hh * 8;
            #pragma unroll
            for (int ni = 0; ni < 4; ni++) {
                float v0 = c[mi][ni][hh * 2 + 0];
                float v1 = c[mi][ni][hh * 2 + 1];
                if (EPI >= 1) {
                    v0 = (v0 > 0.0f) ? v0 : expm1f(v0);
                    v1 = (v1 > 0.0f) ? v1 : expm1f(v1);
                }
                if (EPI <= 1) { v0 = totf32(v0); v1 = totf32(v1); }
                long ci = rg * ldc + bcol + n0 + ni * 8 + (l & 3) * 2;
                if (EPI == 2) {
                    float2 rv = *(const float2*)&Rb[ci];
                    v0 += rv.x; v1 += rv.y;
                }
                float2 o; o.x = v0; o.y = v1;
                *(float2*)&Cb[ci] = o;
            }
        }
    }
}

// ----------------------------------------------------------------------------
// elementwise tf32-round copy
// ----------------------------------------------------------------------------
__global__ void __launch_bounds__(256)
round_copy(const float4* __restrict__ in, float4* __restrict__ out, long n4)
{
    long i = (long)blockIdx.x * 256 + threadIdx.x;
    if (i < n4) {
        float4 v = in[i];
        v.x = totf32(v.x); v.y = totf32(v.y); v.z = totf32(v.z); v.w = totf32(v.w);
        out[i] = v;
    }
}

// ----------------------------------------------------------------------------
// fast exp (FMA only)
// ----------------------------------------------------------------------------
__device__ __forceinline__ float fexp(float x) {
    float y = x * 1.4426950408889634f;
    y = fmaxf(y, -126.0f);
    float r = y + 12582912.0f;
    float fn = r - 12582912.0f;
    int   n  = (int)fn;
    float f  = y - fn;
    float p = 1.3400e-3f;
    p = fmaf(p, f, 9.6784351e-3f);
    p = fmaf(p, f, 5.5503426e-2f);
    p = fmaf(p, f, 2.4022652e-1f);
    p = fmaf(p, f, 6.9314718e-1f);
    p = fmaf(p, f, 1.0f);
    return __int_as_float(__float_as_int(p) + (n << 23));
}

// ----------------------------------------------------------------------------
// f1/f2: warp-per-(row,head) dual dot products, float4 + shuffle reduce
// ----------------------------------------------------------------------------
__global__ void __launch_bounds__(256)
fvec_kernel(const float* __restrict__ Wh, const float* __restrict__ a,
            float* __restrict__ f1, float* __restrict__ f2, int nh)
{
    int gw = (blockIdx.x * 256 + threadIdx.x) >> 5;
    int l = threadIdx.x & 31;
    if (gw >= MM * nh) return;
    int h = gw / MM;
    const float4* wv = (const float4*)(Wh + (long)gw * DD);
    const float4* a1 = (const float4*)(a + (long)h * 2 * DD);
    const float4* a2 = (const float4*)(a + (long)h * 2 * DD + DD);
    float s1 = 0.0f, s2 = 0.0f;
    #pragma unroll
    for (int i = 0; i < DD / 128; i++) {
        int idx = l + i * 32;
        float4 v = wv[idx], x = a1[idx], y = a2[idx];
        s1 += v.x * x.x + v.y * x.y + v.z * x.z + v.w * x.w;
        s2 += v.x * y.x + v.y * y.y + v.z * y.z + v.w * y.w;
    }
    #pragma unroll
    for (int o = 16; o; o >>= 1) {
        s1 += __shfl_xor_sync(0xFFFFFFFFu, s1, o);
        s2 += __shfl_xor_sync(0xFFFFFFFFu, s2, o);
    }
    if (l == 0) { f1[gw] = s1; f2[gw] = s2; }
}

// ----------------------------------------------------------------------------
// masked softmax rows -> P (rounded); scores kept in registers
// ----------------------------------------------------------------------------
__global__ void __launch_bounds__(256)
attn_rows_kernel(const int* __restrict__ adj,
                 const float* __restrict__ f1, const float* __restrict__ f2,
                 float* __restrict__ P, int nheads)
{
    int r = blockIdx.x;
    int b = r >> 10;
    int t = threadIdx.x;
    int l = t & 31, w = t >> 5;

    __shared__ float wmax[8];
    __shared__ float wsum[8];

    int av[NN / 256];
    const int* arow = adj + (long)r * NN;
    #pragma unroll
    for (int k = 0; k < NN / 256; k++) av[k] = arow[t + k * 256];

    for (int h = 0; h < nheads; h++) {
        float f1v = f1[(long)h * MM + r];
        const float* f2h = f2 + (long)h * MM + (long)b * NN;

        float sv[NN / 256];
        float lmax = -INFINITY;
        #pragma unroll
        for (int k = 0; k < NN / 256; k++) {
            float s = f1v + f2h[t + k * 256];
            s = (s > 0.0f) ? s : ALPHA_LRELU * s;
            sv[k] = s;
            if (av[k]) lmax = fmaxf(lmax, s);
        }
        #pragma unroll
        for (int o = 16; o; o >>= 1)
            lmax = fmaxf(lmax, __shfl_xor_sync(0xFFFFFFFFu, lmax, o));
        if (l == 0) wmax[w] = lmax;
        __syncthreads();
        float m = wmax[0];
        #pragma unroll
        for (int q = 1; q < 8; q++) m = fmaxf(m, wmax[q]);

        float lsum = 0.0f;
        #pragma unroll
        for (int k = 0; k < NN / 256; k++) {
            float e = av[k] ? fexp(sv[k] - m) : 0.0f;
            sv[k] = e;
            lsum += e;
        }
        #pragma unroll
        for (int o = 16; o; o >>= 1)
            lsum += __shfl_xor_sync(0xFFFFFFFFu, lsum, o);
        if (l == 0) wsum[w] = lsum;
        __syncthreads();
        float den = 0.0f;
        #pragma unroll
        for (int q = 0; q < 8; q++) den += wsum[q];
        float rd = 1.0f / den;

        float* Prow = P + (((long)h * BB + b) * NN + (r & 1023)) * NN;
        #pragma unroll
        for (int k = 0; k < NN / 256; k++) Prow[t + k * 256] = totf32(sv[k] * rd);
    }
}

// ----------------------------------------------------------------------------
// classifier: warp-per-row
// ----------------------------------------------------------------------------
__global__ void __launch_bounds__(256)
classifier_kernel(const float* __restrict__ yy, const float* __restrict__ wc,
                  const float* __restrict__ bc, const float* __restrict__ mask,
                  float* __restrict__ scores)
{
    int gw = (blockIdx.x * 256 + threadIdx.x) >> 5;
    int l = threadIdx.x & 31;
    if (gw >= MM) return;
    const float4* y = (const float4*)(yy + (long)gw * DD);
    const float4* wv = (const float4*)wc;
    float s = 0.0f;
    #pragma unroll
    for (int i = 0; i < DD / 128; i++) {
        int idx = l + i * 32;
        float4 a = y[idx], b = wv[idx];
        s += a.x * b.x + a.y * b.y + a.z * b.z + a.w * b.w;
    }
    #pragma unroll
    for (int o = 16; o; o >>= 1) s += __shfl_xor_sync(0xFFFFFFFFu, s, o);
    if (l == 0) {
        float v = s + bc[0];
        scores[gw] = (1.0f / (1.0f + expf(-v))) * mask[gw];
    }
}

// ----------------------------------------------------------------------------
// launch
// ----------------------------------------------------------------------------
extern "C" void kernel_launch(void* const* d_in, const int* in_sizes, int n_in,
                              void* d_out, int out_size)
{
    const float* input_emb = (const float*)d_in[0];
    const int*   adj       = (const int*)d_in[1];
    const float* mask_node = (const float*)d_in[2];
    const float* W_heads   = (const float*)d_in[3];
    const float* a_heads   = (const float*)d_in[4];
    const float* W_out     = (const float*)d_in[5];
    const float* a_out     = (const float*)d_in[6];
    const float* w_cls     = (const float*)d_in[7];
    const float* b_cls     = (const float*)d_in[8];

    float* yy     = (float*)d_out;
    float* scores = (float*)d_out + (long)MM * DD;

    float *p_Xr, *p_Wr, *p_WoR, *p_Wh, *p_xx, *p_Who, *p_P;
    float *p_f1, *p_f2, *p_f1o, *p_f2o;
    cudaGetSymbolAddress((void**)&p_Xr,  g_Xr);
    cudaGetSymbolAddress((void**)&p_Wr,  g_Wr);
    cudaGetSymbolAddress((void**)&p_WoR, g_WoR);
    cudaGetSymbolAddress((void**)&p_Wh,  g_Wh);
    cudaGetSymbolAddress((void**)&p_xx,  g_xx);
    cudaGetSymbolAddress((void**)&p_Who, g_Who);
    cudaGetSymbolAddress((void**)&p_P,   g_P);
    cudaGetSymbolAddress((void**)&p_f1,  g_f1);
    cudaGetSymbolAddress((void**)&p_f2,  g_f2);
    cudaGetSymbolAddress((void**)&p_f1o, g_f1o);
    cudaGetSymbolAddress((void**)&p_f2o, g_f2o);

    cudaFuncSetAttribute(mma_gemm<0>, cudaFuncAttributeMaxDynamicSharedMemorySize, GEMM_SMEM);
    cudaFuncSetAttribute(mma_gemm<1>, cudaFuncAttributeMaxDynamicSharedMemorySize, GEMM_SMEM);
    cudaFuncSetAttribute(mma_gemm<2>, cudaFuncAttributeMaxDynamicSharedMemorySize, GEMM_SMEM);

    const int ZBIG = 1 << 30;

    // 0) tf32-round X, W_heads, W_out (no transposes needed)
    {
        long n4 = (long)MM * DD / 4;
        round_copy<<<(unsigned)((n4 + 255) / 256), 256>>>((const float4*)input_emb, (float4*)p_Xr, n4);
        long w4 = (long)HH * DD * DD / 4;
        round_copy<<<(unsigned)((w4 + 255) / 256), 256>>>((const float4*)W_heads, (float4*)p_Wr, w4);
        round_copy<<<(unsigned)((w4 + 255) / 256), 256>>>((const float4*)W_out, (float4*)p_WoR, w4);
    }

    // 1) Wh[h] = Xr @ Wr[h]   (M=8192, Nc=768, K=768)
    mma_gemm<0><<<dim3(DD / 128, MM / 128, HH), 256, GEMM_SMEM>>>(
        p_Xr, p_Wr, p_Wh, nullptr, DD, DD, DD,
        0L, (long)DD * DD, (long)MM * DD, 0L, ZBIG, 0L);

    // 2) f1/f2
    fvec_kernel<<<(MM * HH * 32 + 255) / 256, 256>>>(p_Wh, a_heads, p_f1, p_f2, HH);

    // 3) attention probs
    attn_rows_kernel<<<MM, 256>>>(adj, p_f1, p_f2, p_P, HH);

    // 4) xx = elu(P @ Wh)   (z = h*BB+b, M=1024, Nc=768, K=1024)
    mma_gemm<1><<<dim3(DD / 128, NN / 128, HH * BB), 256, GEMM_SMEM>>>(
        p_P, p_Wh, p_xx, nullptr, NN, DD, HH * DD,
        (long)NN * NN, (long)NN * DD,
        (long)NN * HH * DD, (long)DD, BB, 0L);

    // 5) Who = xx @ W_out   (M=8192, Nc=768, K=3072)
    mma_gemm<0><<<dim3(DD / 128, MM / 128, 1), 256, GEMM_SMEM>>>(
        p_xx, p_WoR, p_Who, nullptr, HH * DD, DD, DD,
        0L, 0L, 0L, 0L, ZBIG, 0L);

    // 6) f1o/f2o
    fvec_kernel<<<(MM * 32 + 255) / 256, 256>>>(p_Who, a_out, p_f1o, p_f2o, 1);

    // 7) out-layer attention probs
    attn_rows_kernel<<<MM, 256>>>(adj, p_f1o, p_f2o, p_P, 1);

    // 8) yy = elu(P @ Who) + input_emb   (z = b)
    mma_gemm<2><<<dim3(DD / 128, NN / 128, BB), 256, GEMM_SMEM>>>(
        p_P, p_Who, yy, input_emb, NN, DD, DD,
        (long)NN * NN, (long)NN * DD,
        (long)NN * DD, 0L, ZBIG, (long)NN * DD);

    // 9) classifier
    classifier_kernel<<<(MM * 32 + 255) / 256, 256>>>(yy, w_cls, b_cls, mask_node, scores);

    (void)in_sizes; (void)n_in; (void)out_size;
}